// round 15
// baseline (speedup 1.0000x reference)
#include <cuda_runtime.h>
#include <cuda_bf16.h>

#define EPS   1e-6f
#define LN2   0.6931471805599453f
#define RROWS 51            // 255 = 5 * 51
#define OUTW  62            // output cols per warp (warps overlap by one pair)
#define IN_PL  (256 * 256)  // plane stride, input
#define OUT_PL (255 * 255)  // plane stride, output

__device__ __forceinline__ float fast_rcp(float a) {
    float r;
    asm("rcp.approx.f32 %0, %1;" : "=f"(r) : "f"(a));
    return r;
}

__device__ __forceinline__ void row_h(float2 v,
                                      float& hv0, float& hl0,
                                      float& hv1, float& hl1)
{
    float l0 = v.x * __log2f(v.x + EPS);
    float l1 = v.y * __log2f(v.y + EPS);
    float vn = __shfl_down_sync(0xffffffffu, v.x, 1);
    float ln = __shfl_down_sync(0xffffffffu, l0, 1);
    hv0 = v.x + v.y;  hl0 = l0 + l1;
    hv1 = v.y + vn;   hl1 = l1 + ln;
}

__device__ __forceinline__ void emit(float hv0p, float hl0p, float hv1p, float hl1p,
                                     float hv0, float hl0, float hv1, float hl1,
                                     float* po, bool ok0, bool ok1)
{
    float s0  = hv0p + hv0;
    float sl0 = hl0p + hl0;
    float S0  = s0 + EPS;
    float e0  = fmaf(s0, __log2f(S0), -sl0) * fast_rcp(S0) * LN2;
    float s1  = hv1p + hv1;
    float sl1 = hl1p + hl1;
    float S1  = s1 + EPS;
    float e1  = fmaf(s1, __log2f(S1), -sl1) * fast_rcp(S1) * LN2;
    if (ok0) __stcs(po,     e0);
    if (ok1) __stcs(po + 1, e1);
}

__global__ __launch_bounds__(160)
void entropy2x2_k10(const float* __restrict__ x, float* __restrict__ out)
{
    const int lane  = threadIdx.x & 31;
    const int warp  = threadIdx.x >> 5;        // 0..4
    const int pl2   = blockIdx.z;              // 0..255 -> planes 2*pl2, 2*pl2+1
    const int pc    = warp * OUTW + lane * 2;  // 0..310
    const int lc    = min(pc, 254);            // in-bounds, 8B-aligned load col
    const int yBase = blockIdx.y * RROWS;      // 0,51,102,153,204

    const float* __restrict__ p  = x   + (size_t)pl2 * (2 * IN_PL)
                                       + (size_t)yBase * 256 + lc;
    float*       __restrict__ po = out + (size_t)pl2 * (2 * OUT_PL)
                                       + (size_t)yBase * 255 + pc;

    const bool act = (lane < 31);              // lane31 only feeds shfl
    const bool ok0 = act && (pc     < 255);
    const bool ok1 = act && (pc + 1 < 255);

    // ---- prime both plane streams; one prefetch row each in flight ----
    float2 vA  = *reinterpret_cast<const float2*>(p);
    float2 vB  = *reinterpret_cast<const float2*>(p + IN_PL);   // imm offset
    p += 256;
    float2 vpA = *reinterpret_cast<const float2*>(p);
    float2 vpB = *reinterpret_cast<const float2*>(p + IN_PL);
    p += 256;

    float hv0A, hl0A, hv1A, hl1A, hv0B, hl0B, hv1B, hl1B;
    row_h(vA, hv0A, hl0A, hv1A, hl1A);
    row_h(vB, hv0B, hl0B, hv1B, hl1B);

    // ---- main loop: 50 iterations, two independent chains interleaved ----
    #pragma unroll 2
    for (int r = 0; r < RROWS - 1; r++) {
        float2 cA = vpA, cB = vpB;
        vpA = *reinterpret_cast<const float2*>(p);
        vpB = *reinterpret_cast<const float2*>(p + IN_PL);
        p += 256;

        float a0, b0, c0, d0, a1, b1, c1, d1;
        row_h(cA, a0, b0, c0, d0);
        row_h(cB, a1, b1, c1, d1);
        emit(hv0A, hl0A, hv1A, hl1A, a0, b0, c0, d0, po,          ok0, ok1);
        emit(hv0B, hl0B, hv1B, hl1B, a1, b1, c1, d1, po + OUT_PL, ok0, ok1);

        hv0A = a0; hl0A = b0; hv1A = c0; hl1A = d0;
        hv0B = a1; hl0B = b1; hv1B = c1; hl1B = d1;
        po += 255;
    }

    // ---- peeled last row ----
    {
        float a0, b0, c0, d0, a1, b1, c1, d1;
        row_h(vpA, a0, b0, c0, d0);
        row_h(vpB, a1, b1, c1, d1);
        emit(hv0A, hl0A, hv1A, hl1A, a0, b0, c0, d0, po,          ok0, ok1);
        emit(hv0B, hl0B, hv1B, hl1B, a1, b1, c1, d1, po + OUT_PL, ok0, ok1);
    }
}

extern "C" void kernel_launch(void* const* d_in, const int* in_sizes, int n_in,
                              void* d_out, int out_size)
{
    const float* x = (const float*)d_in[0];
    float* out = (float*)d_out;

    // 5 warps x 62 cols = 310 >= 255; 5 strips of 51 rows; 256 plane-pairs.
    dim3 block(160);
    dim3 grid(1, 5, 256);
    entropy2x2_k10<<<grid, block>>>(x, out);
}

// round 16
// speedup vs baseline: 1.5724x; 1.5724x over previous
#include <cuda_runtime.h>
#include <cuda_bf16.h>

#define EPS   1e-6f
#define LN2   0.6931471805599453f
#define RROWS 51   // 255 = 5 * 51 -> uniform trip count
#define OUTW  31   // outputs per warp (warps overlap by 1 column)

__device__ __forceinline__ float fast_rcp(float a) {
    float r;
    asm("rcp.approx.f32 %0, %1;" : "=f"(r) : "f"(a));
    return r;
}

// One pixel column per lane: one log per pixel, neighbor v/l via shfl.
__device__ __forceinline__ void row_h(float v, float& hv, float& hl)
{
    float l  = v * __log2f(v + EPS);
    float vn = __shfl_down_sync(0xffffffffu, v, 1);
    float ln = __shfl_down_sync(0xffffffffu, l, 1);
    hv = v + vn;
    hl = l + ln;
}

__device__ __forceinline__ void emit(float hv_p, float hl_p, float hv, float hl,
                                     float* po, bool ok)
{
    float s  = hv_p + hv;                 // 2x2 window sum
    float sl = hl_p + hl;                 // sum of w*lg2(w+eps)
    float S  = s + EPS;
    float e  = fmaf(s, __log2f(S), -sl) * fast_rcp(S) * LN2;
    if (ok) __stcs(po, e);                // predicated, no branch
}

__global__ __launch_bounds__(288)
void entropy2x2_k11(const float* __restrict__ x, float* __restrict__ out)
{
    const int lane  = threadIdx.x & 31;
    const int warp  = threadIdx.x >> 5;        // 0..8
    const int plane = blockIdx.z;              // 0..511
    const int oc    = warp * OUTW + lane;      // output col, 0..278
    const int lc    = min(oc, 255);            // clamped load col (coalesced)
    const int yBase = blockIdx.y * RROWS;      // 0,51,102,153,204

    const float* __restrict__ p  = x   + (size_t)plane * (256 * 256)
                                       + (size_t)yBase * 256 + lc;
    float*       __restrict__ po = out + (size_t)plane * (255 * 255)
                                       + (size_t)yBase * 255 + oc;

    const bool ok = (lane < OUTW) && (oc < 255);

    // ---- prime row yBase; prefetch row yBase+1 (depth-1) ----
    float v  = p[0];                           p += 256;
    float vp = p[0];                           p += 256;   // in flight

    float hv_p, hl_p;
    row_h(v, hv_p, hl_p);

    // ---- main loop: 50 iterations, load for r+2 issued before emit(r) ----
    #pragma unroll 5
    for (int r = 0; r < RROWS - 1; r++) {
        float vc = vp;
        vp = p[0];                             p += 256;   // prefetch next row

        float hv, hl;
        row_h(vc, hv, hl);
        emit(hv_p, hl_p, hv, hl, po, ok);

        hv_p = hv;
        hl_p = hl;
        po += 255;
    }

    // ---- peeled last row: consume final prefetch, no further load ----
    {
        float hv, hl;
        row_h(vp, hv, hl);
        emit(hv_p, hl_p, hv, hl, po, ok);
    }
}

extern "C" void kernel_launch(void* const* d_in, const int* in_sizes, int n_in,
                              void* d_out, int out_size)
{
    const float* x = (const float*)d_in[0];
    float* out = (float*)d_out;

    // 9 warps x 31 output cols = 279 >= 255; 5 row-strips of 51 cover 255 rows.
    dim3 block(288);
    dim3 grid(1, 5, 512);
    entropy2x2_k11<<<grid, block>>>(x, out);
}